// round 5
// baseline (speedup 1.0000x reference)
#include <cuda_runtime.h>
#include <math.h>

#define BB 2
#define NN 512
#define DIN 512
#define DM 256
#define C2LOG2E 2.885390081777927f   // 2*log2(e)

// scratch (static device globals — no allocation)
__device__ float g_h[BB * NN * DM];    // h[b][n][d] = tanh(x@Wx+bx)
__device__ float g_p[BB * NN * DM];    // P row-major: exp2(c*(u+bp))[b][n][d]
__device__ float g_qt[BB * DM * NN];   // Q transposed: exp2(-c*u)[b][d][n]

__device__ __forceinline__ float ex2_fast(float x) {
    float y; asm("ex2.approx.f32 %0, %1;" : "=f"(y) : "f"(x)); return y;
}
__device__ __forceinline__ float rcp_fast(float x) {
    float y; asm("rcp.approx.f32 %0, %1;" : "=f"(y) : "f"(x)); return y;
}

// ---------------------------------------------------------------------------
// Kernel A: h = tanh(x @ Wx + bx); P (row-major) / Q (transposed).
// 8 rows per block -> 128 blocks (single wave), 256 threads (thread t = col d)
// ---------------------------------------------------------------------------
__global__ __launch_bounds__(256) void kA(const float* __restrict__ x,
                                          const float* __restrict__ pos,
                                          const float* __restrict__ Wx,
                                          const float* __restrict__ bx,
                                          const float* __restrict__ Wp,
                                          const float* __restrict__ bp) {
    __shared__ float s_x[DIN][8];    // 16KB, x tile transposed
    const int t = threadIdx.x;
    const int row0 = blockIdx.x * 8;

    for (int e = t; e < DIN * 8; e += 256) {
        int r = e >> 9, c = e & (DIN - 1);
        s_x[c][r] = x[(row0 + r) * DIN + c];     // coalesced
    }
    __syncthreads();

    const float bias = bx[t];
    float a[8];
#pragma unroll
    for (int r = 0; r < 8; r++) a[r] = bias;
#pragma unroll 4
    for (int k = 0; k < DIN; k++) {
        float wv = Wx[k * DM + t];               // coalesced, L2-hot
        float4 xA = *(const float4*)&s_x[k][0];  // broadcast LDS.128
        float4 xB = *(const float4*)&s_x[k][4];
        a[0] += xA.x * wv; a[1] += xA.y * wv;
        a[2] += xA.z * wv; a[3] += xA.w * wv;
        a[4] += xB.x * wv; a[5] += xB.y * wv;
        a[6] += xB.z * wv; a[7] += xB.w * wv;
    }
#pragma unroll
    for (int r = 0; r < 8; r++) g_h[(row0 + r) * DM + t] = tanhf(a[r]);

    const int b = row0 / NN;
    const int n0 = row0 % NN;
    const float w0 = Wp[0 * DM + t], w1 = Wp[1 * DM + t];
    const float w2 = Wp[2 * DM + t], w3 = Wp[3 * DM + t];
    const float bpv = bp[t];
#pragma unroll
    for (int r = 0; r < 8; r++) {
        const float* p = pos + (row0 + r) * 4;
        float u = p[0] * w0 + p[1] * w1 + p[2] * w2 + p[3] * w3;
        g_p[(row0 + r) * DM + t] = ex2_fast(C2LOG2E * (u + bpv));   // coalesced
        g_qt[(b * DM + t) * NN + n0 + r] = ex2_fast(-C2LOG2E * u);
    }
}

// ---------------------------------------------------------------------------
// Kernel Score: raw scores -> attn_out.  Block = 8 query rows x 128 j's.
// grid = (B*N/8) * (N/128) = 512 blocks, 128 threads. Thread owns one j.
// score_ij = W - 2*sum_d w_d / (1 + P_i[d]*Q_j[d])
// ---------------------------------------------------------------------------
__global__ __launch_bounds__(128) void kScore(const float* __restrict__ w,
                                              float* __restrict__ attn_out) {
    __shared__ float s_pi[DM][8];   // 8 P rows, 8KB
    __shared__ float s_wn[DM];      // -2*w, 1KB
    __shared__ float s_W;

    const int t = threadIdx.x;
    const int jt = blockIdx.x & 3;            // 4 j-tiles of 128
    const int it = blockIdx.x >> 2;           // row-octet index [0,128)
    const int b  = it >> 6;                   // NN/8 = 64 octets per batch
    const int i0 = (it & 63) * 8;
    const int j  = jt * 128 + t;

    // -2*w and W = sum(w)
    {
        float wv0 = w[t], wv1 = w[t + 128];
        s_wn[t] = -2.0f * wv0;
        s_wn[t + 128] = -2.0f * wv1;
        if (t < 32) {
            float s = 0.f;
#pragma unroll
            for (int k = 0; k < 8; k++) s += w[t + 32 * k];
#pragma unroll
            for (int o = 16; o; o >>= 1) s += __shfl_xor_sync(0xffffffffu, s, o);
            if (t == 0) s_W = s;
        }
    }
    // coalesced load of eight P rows (row-major, 1KB each)
    {
        const float* prow = g_p + (b * NN + i0) * DM;
        for (int e = t; e < 8 * DM; e += 128) {
            int r = e >> 8, d = e & (DM - 1);
            s_pi[d][r] = prow[r * DM + d];
        }
    }
    __syncthreads();
    const float W = s_W;

    float acc[8];
#pragma unroll
    for (int r = 0; r < 8; r++) acc[r] = 0.f;

    const float* qp = g_qt + b * DM * NN + j;
    float qbuf[4];
#pragma unroll
    for (int p = 0; p < 4; p++) qbuf[p] = qp[p * NN];

    for (int d0 = 0; d0 < DM; d0 += 4) {
        float qc[4];
#pragma unroll
        for (int p = 0; p < 4; p++) qc[p] = qbuf[p];
        if (d0 + 4 < DM) {
#pragma unroll
            for (int p = 0; p < 4; p++) qbuf[p] = qp[(d0 + 4 + p) * NN];
        }
#pragma unroll
        for (int dd = 0; dd < 4; dd++) {
            const int d = d0 + dd;
            const float wn = s_wn[d];
            const float4 piA = *(const float4*)&s_pi[d][0];  // broadcast LDS.128
            const float4 piB = *(const float4*)&s_pi[d][4];
            const float qj = qc[dd];
            float de0 = fmaf(piA.x, qj, 1.0f);
            float de1 = fmaf(piA.y, qj, 1.0f);
            float de2 = fmaf(piA.z, qj, 1.0f);
            float de3 = fmaf(piA.w, qj, 1.0f);
            float de4 = fmaf(piB.x, qj, 1.0f);
            float de5 = fmaf(piB.y, qj, 1.0f);
            float de6 = fmaf(piB.z, qj, 1.0f);
            float de7 = fmaf(piB.w, qj, 1.0f);
            float r01 = rcp_fast(de0 * de1);
            float r23 = rcp_fast(de2 * de3);
            float r45 = rcp_fast(de4 * de5);
            float r67 = rcp_fast(de6 * de7);
            float w01 = wn * r01, w23 = wn * r23;
            float w45 = wn * r45, w67 = wn * r67;
            acc[0] += w01 * de1;  acc[1] += w01 * de0;
            acc[2] += w23 * de3;  acc[3] += w23 * de2;
            acc[4] += w45 * de5;  acc[5] += w45 * de4;
            acc[6] += w67 * de7;  acc[7] += w67 * de6;
        }
    }
    float* arow = attn_out + (b * NN + i0) * NN + j;
#pragma unroll
    for (int r = 0; r < 8; r++) arow[r * NN] = W + acc[r];
}

// ---------------------------------------------------------------------------
// Kernel SoftOut: masked softmax over 8 rows + output GEMM.
// grid = B*N/8 = 128 blocks (single wave), 512 threads.
// ---------------------------------------------------------------------------
__global__ __launch_bounds__(512) void kSoftOut(const int* __restrict__ mask,
                                                float* __restrict__ out,
                                                float* __restrict__ attn_out) {
    __shared__ float s_attn[8][NN];   // scores -> probs, 16KB

    const int t = threadIdx.x;
    const int blk = blockIdx.x;
    const int b = blk >> 6;                 // NN/8 = 64 octets per batch
    const int i0 = (blk & 63) * 8;

    // load 8 score rows (coalesced float4)
    {
        const float4* src = (const float4*)(attn_out + (b * NN + i0) * NN);
        float4* dst = (float4*)&s_attn[0][0];
        for (int e = t; e < 8 * NN / 4; e += 512) dst[e] = src[e];
    }
    __syncthreads();

    // masked softmax: warp wid (<8) handles row i0+wid, vectorized int4/float4
    const int wid = t >> 5, lane = t & 31;
    if (wid < 8) {
        const int i = i0 + wid;
        const int4* m4 = (const int4*)(mask + (b * NN + i) * NN);
        float4* s4 = (float4*)&s_attn[wid][0];
        int4 mv[4];
        float4 sv[4];
#pragma unroll
        for (int k = 0; k < 4; k++) {
            mv[k] = m4[lane + 32 * k];
            sv[k] = s4[lane + 32 * k];
        }
        float mx = -INFINITY;
#pragma unroll
        for (int k = 0; k < 4; k++) {
            if (mv[k].x) mx = fmaxf(mx, sv[k].x);
            if (mv[k].y) mx = fmaxf(mx, sv[k].y);
            if (mv[k].z) mx = fmaxf(mx, sv[k].z);
            if (mv[k].w) mx = fmaxf(mx, sv[k].w);
        }
#pragma unroll
        for (int o = 16; o; o >>= 1) mx = fmaxf(mx, __shfl_xor_sync(0xffffffffu, mx, o));
        float sum = 0.f;
#pragma unroll
        for (int k = 0; k < 4; k++) {
            sv[k].x = mv[k].x ? __expf(sv[k].x - mx) : 0.f;
            sv[k].y = mv[k].y ? __expf(sv[k].y - mx) : 0.f;
            sv[k].z = mv[k].z ? __expf(sv[k].z - mx) : 0.f;
            sv[k].w = mv[k].w ? __expf(sv[k].w - mx) : 0.f;
            sum += sv[k].x + sv[k].y + sv[k].z + sv[k].w;
        }
#pragma unroll
        for (int o = 16; o; o >>= 1) sum += __shfl_xor_sync(0xffffffffu, sum, o);
        const float inv = (sum > 0.f) ? 1.f / sum : 0.f;
        float4* arow4 = (float4*)(attn_out + (b * NN + i) * NN);
#pragma unroll
        for (int k = 0; k < 4; k++) {
            sv[k].x *= inv; sv[k].y *= inv; sv[k].z *= inv; sv[k].w *= inv;
            s4[lane + 32 * k] = sv[k];
            arow4[lane + 32 * k] = sv[k];
        }
    }
    __syncthreads();

    // output: thread t -> d = t&255, rows {4*g .. 4*g+3} with g = t>>8
    const int d = t & (DM - 1);
    const int g = t >> 8;                 // 0 or 1
    float o0 = 0.f, o1 = 0.f, o2 = 0.f, o3 = 0.f;
    const float* hb = g_h + b * NN * DM + d;
    const float4* p0 = (const float4*)&s_attn[4 * g + 0][0];
    const float4* p1 = (const float4*)&s_attn[4 * g + 1][0];
    const float4* p2 = (const float4*)&s_attn[4 * g + 2][0];
    const float4* p3 = (const float4*)&s_attn[4 * g + 3][0];
#pragma unroll 2
    for (int j4 = 0; j4 < NN / 4; j4++) {
        float h0 = hb[(4 * j4 + 0) * DM];
        float h1 = hb[(4 * j4 + 1) * DM];
        float h2 = hb[(4 * j4 + 2) * DM];
        float h3 = hb[(4 * j4 + 3) * DM];
        float4 a0 = p0[j4];  // broadcast LDS.128
        float4 a1 = p1[j4];
        float4 a2 = p2[j4];
        float4 a3 = p3[j4];
        o0 += a0.x * h0 + a0.y * h1 + a0.z * h2 + a0.w * h3;
        o1 += a1.x * h0 + a1.y * h1 + a1.z * h2 + a1.w * h3;
        o2 += a2.x * h0 + a2.y * h1 + a2.z * h2 + a2.w * h3;
        o3 += a3.x * h0 + a3.y * h1 + a3.z * h2 + a3.w * h3;
    }
    out[(b * NN + i0 + 4 * g + 0) * DM + d] = o0;
    out[(b * NN + i0 + 4 * g + 1) * DM + d] = o1;
    out[(b * NN + i0 + 4 * g + 2) * DM + d] = o2;
    out[(b * NN + i0 + 4 * g + 3) * DM + d] = o3;
}

// ---------------------------------------------------------------------------
extern "C" void kernel_launch(void* const* d_in, const int* in_sizes, int n_in,
                              void* d_out, int out_size) {
    const float* x    = (const float*)d_in[0];  // [2,512,512]
    const float* pos  = (const float*)d_in[1];  // [2,512,4]
    const int*   mask = (const int*)  d_in[2];  // [2,512,512]
    const float* Wx   = (const float*)d_in[3];  // [512,256]
    const float* bx   = (const float*)d_in[4];  // [256]
    const float* Wp   = (const float*)d_in[5];  // [4,256]
    const float* bp   = (const float*)d_in[6];  // [256]
    const float* w    = (const float*)d_in[7];  // [256]

    float* out      = (float*)d_out;            // [2,512,256]
    float* attn_out = out + BB * NN * DM;       // [2,512,512]

    kA<<<BB * NN / 8, 256>>>(x, pos, Wx, bx, Wp, bp);
    kScore<<<(BB * NN / 8) * (NN / 128), 128>>>(w, attn_out);
    kSoftOut<<<BB * NN / 8, 512>>>(mask, out, attn_out);
}